// round 3
// baseline (speedup 1.0000x reference)
#include <cuda_runtime.h>
#include <cstdint>

// ---------------------------------------------------------------------------
// MalConv fused:  emb-lookup + dual conv1d(k=stride=500) as GEMM + GLU + relu
//                 + global max pool + FC
//
//   C[16000,256] = E[16000,4000] x Wpack[4000,256]
//   E[p, k*8+c] = emb[x[b, p*500+k], c]   (emb row 256 is zero => pad free)
//   cols 0..127 -> g1 (W1), cols 128..255 -> g2 (W2)
//   h = relu(g1 * sigmoid(g2)); m[b,o] = max_p h; out = m @ fcW^T + fcb
//
// NOTE: x is int32 on device (JAX canonicalizes int64 -> int32 w/o x64 mode).
// ---------------------------------------------------------------------------

#define KERNEL_K   500
#define PATCHES_B  2000
#define BATCH      8
#define SEQ_L      1000000
#define NOUT       256          // 128 (g1) + 128 (g2)
#define TM         40           // patches per CTA  (50 CTAs per batch)
#define KB         32           // K values per tile = 4 k-positions * 8 channels
#define KITERS     125          // 500 / 4

__device__ __align__(16) float g_Wpack[4000 * NOUT];  // [K][o], K = k*8 + c
__device__ int g_m[BATCH * 128];                      // max accum (float bits, >=0)

// ---------------------------------------------------------------------------
__global__ void pack_kernel(const float* __restrict__ W1,
                            const float* __restrict__ W2) {
    int i = blockIdx.x * 256 + threadIdx.x;
    if (i < BATCH * 128) g_m[i] = 0;                // zero max accumulator
    if (i >= 4000 * NOUT) return;
    int o = i & 255;
    int K = i >> 8;
    int k = K >> 3;          // 0..499
    int c = K & 7;           // 0..7
    float v = (o < 128) ? W1[o * 4000 + c * KERNEL_K + k]
                        : W2[(o - 128) * 4000 + c * KERNEL_K + k];
    g_Wpack[i] = v;
}

// ---------------------------------------------------------------------------
__global__ __launch_bounds__(256)
void malconv_kernel(const int* __restrict__ x,
                    const float* __restrict__ emb,
                    const float* __restrict__ b1,
                    const float* __restrict__ b2) {
    __shared__ __align__(16) float sEmb[257 * 8];   // 8224 B embedding table
    __shared__ __align__(16) float sW[KB * NOUT];   // 32 KB weight tile [kk][o]
    __shared__ __align__(16) float sE[TM * KB];     // 5 KB   E tile     [p][kk]

    const int tid = threadIdx.x;
    const int tx  = tid & 31;              // output group: o = tx*4 .. tx*4+3
    const int ty  = tid >> 5;              // patch group : 5 patches
    const int b   = blockIdx.y;
    const int pbase = blockIdx.x * TM;

    for (int i = tid; i < 257 * 8; i += 256) sEmb[i] = emb[i];

    float acc1[5][4];
    float acc2[5][4];
#pragma unroll
    for (int i = 0; i < 5; i++)
#pragma unroll
        for (int j = 0; j < 4; j++) { acc1[i][j] = 0.f; acc2[i][j] = 0.f; }

    const size_t xbase = (size_t)b * SEQ_L + (size_t)pbase * KERNEL_K;
    float4* sW4 = (float4*)sW;

    for (int iter = 0; iter < KITERS; iter++) {
        __syncthreads();   // protects sW/sE of previous iter (and sEmb, iter 0)

        // --- load weight tile: 32x256 floats, fully coalesced ---
        const float4* wsrc = (const float4*)(g_Wpack + iter * (KB * NOUT));
#pragma unroll
        for (int j = 0; j < 8; j++)
            sW4[tid + j * 256] = wsrc[tid + j * 256];

        // --- build E tile: 40 patches x 4 k-positions ---
        if (tid < TM * 4) {
            int p  = tid >> 2;
            int kp = tid & 3;
            int v  = x[xbase + (size_t)p * KERNEL_K + iter * 4 + kp];
            const float4* er = (const float4*)(sEmb + (v << 3));
            float4* dst = (float4*)(sE + p * KB + kp * 8);
            dst[0] = er[0];
            dst[1] = er[1];
        }
        __syncthreads();

        // --- FFMA mainloop: 32 kk x (5 patches x 8 outputs) ---
#pragma unroll
        for (int kk = 0; kk < KB; kk++) {
            float4 w1 = sW4[kk * 64 + tx];        // cols tx*4..+3      (g1)
            float4 w2 = sW4[kk * 64 + 32 + tx];   // cols 128+tx*4..+3  (g2)
#pragma unroll
            for (int i = 0; i < 5; i++) {
                float e = sE[(ty * 5 + i) * KB + kk];
                acc1[i][0] += e * w1.x; acc1[i][1] += e * w1.y;
                acc1[i][2] += e * w1.z; acc1[i][3] += e * w1.w;
                acc2[i][0] += e * w2.x; acc2[i][1] += e * w2.y;
                acc2[i][2] += e * w2.z; acc2[i][3] += e * w2.w;
            }
        }
    }

    // --- epilogue: bias + GLU + relu + per-thread max over 5 patches ---
    float hb1[4], hb2[4], hm[4];
#pragma unroll
    for (int j = 0; j < 4; j++) {
        hb1[j] = b1[tx * 4 + j];
        hb2[j] = b2[tx * 4 + j];
        hm[j]  = 0.f;
    }
#pragma unroll
    for (int i = 0; i < 5; i++) {
#pragma unroll
        for (int j = 0; j < 4; j++) {
            float g1 = acc1[i][j] + hb1[j];
            float g2 = acc2[i][j] + hb2[j];
            float sg = 1.f / (1.f + expf(-g2));
            float h  = fmaxf(g1 * sg, 0.f);
            hm[j] = fmaxf(hm[j], h);
        }
    }
#pragma unroll
    for (int j = 0; j < 4; j++)
        atomicMax(&g_m[b * 128 + tx * 4 + j], __float_as_int(hm[j]));
}

// ---------------------------------------------------------------------------
__global__ void fc_kernel(const float* __restrict__ fcW,
                          const float* __restrict__ fcb,
                          float* __restrict__ out) {
    int w    = threadIdx.x >> 5;
    int lane = threadIdx.x & 31;
    for (int pair = w; pair < BATCH * 2; pair += 8) {
        int b = pair >> 1;
        int j = pair & 1;
        float s = 0.f;
        for (int o = lane; o < 128; o += 32)
            s += __int_as_float(g_m[b * 128 + o]) * fcW[j * 128 + o];
#pragma unroll
        for (int off = 16; off; off >>= 1)
            s += __shfl_down_sync(0xFFFFFFFFu, s, off);
        if (lane == 0) out[b * 2 + j] = s + fcb[j];
    }
}

// ---------------------------------------------------------------------------
extern "C" void kernel_launch(void* const* d_in, const int* in_sizes, int n_in,
                              void* d_out, int out_size) {
    const int*   x   = (const int*)d_in[0];
    const float* emb = (const float*)d_in[1];
    const float* W1  = (const float*)d_in[2];
    const float* b1  = (const float*)d_in[3];
    const float* W2  = (const float*)d_in[4];
    const float* b2  = (const float*)d_in[5];
    const float* fcW = (const float*)d_in[6];
    const float* fcb = (const float*)d_in[7];
    float*       out = (float*)d_out;

    pack_kernel<<<(4000 * NOUT + 255) / 256, 256>>>(W1, W2);
    malconv_kernel<<<dim3(PATCHES_B / TM, BATCH), 256>>>(x, emb, b1, b2);
    fc_kernel<<<1, 256>>>(fcW, fcb, out);
}